// round 2
// baseline (speedup 1.0000x reference)
#include <cuda_runtime.h>
#include <stdint.h>

// out[b,n,j] = X[b,n,10j+9] / X[b,n,10j] - 2
// X: (64, 512, 4000) fp32 contiguous; out: (64, 512, 400) fp32.
//
// R2: stage rows through shared memory with fully coalesced float4 loads
// (100% sector utilization per L2 request), then gather first/last from SMEM.
// DRAM traffic is invariant (every 32B sector of X is needed); this targets
// request efficiency to lift achieved HBM bandwidth.

static constexpr int T_LEN      = 4000;   // floats per row
static constexpr int W_LEN      = 400;    // windows per row
static constexpr int ROWS_TOTAL = 64 * 512;          // 32768
static constexpr int ROWS_PER_BLK = 2;
static constexpr int THREADS    = 256;
static constexpr int SMEM_FLOATS = ROWS_PER_BLK * T_LEN;       // 8000
static constexpr int SMEM_VEC4   = SMEM_FLOATS / 4;            // 2000
static constexpr int OUT_PER_BLK = ROWS_PER_BLK * W_LEN;       // 800

__global__ __launch_bounds__(THREADS) void ts_return_kernel(
    const float* __restrict__ X, float* __restrict__ out)
{
    __shared__ float s[SMEM_FLOATS];

    const uint32_t tid = threadIdx.x;
    const uint32_t rowBase = blockIdx.x * ROWS_PER_BLK;

    // Coalesced float4 load of 2 rows (16000 B each row, 16B-aligned since
    // row stride = 4000*4 = 16000 B and X base is malloc-aligned).
    const float4* __restrict__ src =
        (const float4*)(X + (size_t)rowBase * T_LEN);
    float4* __restrict__ sv = (float4*)s;

    #pragma unroll
    for (int k = 0; k < (SMEM_VEC4 + THREADS - 1) / THREADS; k++) {
        uint32_t i = tid + (uint32_t)k * THREADS;
        if (i < SMEM_VEC4) sv[i] = src[i];
    }
    __syncthreads();

    // 800 outputs, 256 threads -> up to 4 each; stores coalesced.
    float* __restrict__ dst = out + (size_t)rowBase * W_LEN;
    #pragma unroll
    for (int k = 0; k < (OUT_PER_BLK + THREADS - 1) / THREADS; k++) {
        uint32_t j = tid + (uint32_t)k * THREADS;
        if (j < OUT_PER_BLK) {
            // j in [0,800): row_in_blk = j/400, window = j%400
            uint32_t r  = (j >= W_LEN) ? 1u : 0u;
            uint32_t w  = j - r * W_LEN;
            uint32_t base = r * T_LEN + 10u * w;
            float first = s[base];
            float last  = s[base + 9];
            dst[j] = __fdividef(last, first) - 2.0f;
        }
    }
}

extern "C" void kernel_launch(void* const* d_in, const int* in_sizes, int n_in,
                              void* d_out, int out_size)
{
    const float* X = (const float*)d_in[0];
    float* out = (float*)d_out;
    int blocks = ROWS_TOTAL / ROWS_PER_BLK;   // 16384
    ts_return_kernel<<<blocks, THREADS>>>(X, out);
}

// round 3
// speedup vs baseline: 1.1057x; 1.1057x over previous
#include <cuda_runtime.h>
#include <stdint.h>

// out[b,n,j] = X[b,n,10j+9] / X[b,n,10j] - 2
// X: (64, 512, 4000) fp32; out: (64, 512, 400) fp32.
//
// R3: one thread per 4 windows = one 160B (sector-aligned) period.
// 6 independent LDG.128 per thread (high MLP, 75% byte utilization of
// touched region), 1 coalesced STG.128 for the 4 results. No smem/barriers.

static constexpr int T_LEN    = 4000;               // floats per row
static constexpr int W_LEN    = 400;                // windows per row
static constexpr int QUADS_PER_ROW = W_LEN / 4;     // 100
static constexpr int N_ROWS   = 64 * 512;           // 32768
static constexpr int N_THREADS_TOTAL = N_ROWS * QUADS_PER_ROW;  // 3,276,800

__global__ __launch_bounds__(256) void ts_return_kernel(
    const float* __restrict__ X, float* __restrict__ out)
{
    uint32_t idx = blockIdx.x * blockDim.x + threadIdx.x;
    if (idx >= (uint32_t)N_THREADS_TOTAL) return;

    uint32_t row = idx / QUADS_PER_ROW;
    uint32_t q   = idx - row * QUADS_PER_ROW;

    // Period base: 40 floats = 160 bytes, 16B-aligned.
    const float4* __restrict__ p =
        (const float4*)(X + (size_t)row * T_LEN + (uint32_t)(40u * q));

    // Needed elements within the period: e0,e9 | e10,e19 | e20,e29 | e30,e39
    float4 v0 = p[0];   // e0..e3
    float4 v2 = p[2];   // e8..e11   -> e9 (.y), e10 (.z)
    float4 v4 = p[4];   // e16..e19  -> e19 (.w)
    float4 v5 = p[5];   // e20..e23  -> e20 (.x)
    float4 v7 = p[7];   // e28..e31  -> e29 (.y), e30 (.z)
    float4 v9 = p[9];   // e36..e39  -> e39 (.w)

    float4 o;
    o.x = __fdividef(v2.y, v0.x) - 2.0f;   // e9 / e0
    o.y = __fdividef(v4.w, v2.z) - 2.0f;   // e19 / e10
    o.z = __fdividef(v7.y, v5.x) - 2.0f;   // e29 / e20
    o.w = __fdividef(v9.w, v7.z) - 2.0f;   // e39 / e30

    // Output: 4 consecutive floats, 16B-aligned, coalesced across the warp.
    float4* __restrict__ dst =
        (float4*)(out + (size_t)row * W_LEN + (uint32_t)(4u * q));
    *dst = o;
}

extern "C" void kernel_launch(void* const* d_in, const int* in_sizes, int n_in,
                              void* d_out, int out_size)
{
    const float* X = (const float*)d_in[0];
    float* out = (float*)d_out;
    int threads = 256;
    int blocks = (N_THREADS_TOTAL + threads - 1) / threads;   // 12800
    ts_return_kernel<<<blocks, threads>>>(X, out);
}

// round 4
// speedup vs baseline: 1.2138x; 1.0978x over previous
#include <cuda_runtime.h>
#include <stdint.h>

// out_flat[4p+k] = X_flat[40p+10k+9] / X_flat[40p+10k] - 2,  k=0..3
// (row stride 4000 = 100 periods of 40, so flat processing is exact).
//
// R4: memcpy-identical load stream. Each warp owns a 640-float tile:
//   5 dense coalesced LDG.128 rounds -> warp-local SMEM -> __syncwarp
//   -> stride-10 LDS gather -> 2 coalesced STG.32 rounds.
// No block barrier (R2's failure mode), no wasted L1/L2 bytes (R3's).

static constexpr long long N_FLOATS = 64LL * 512 * 4000;        // 131,072,000
static constexpr int TILE_F4   = 160;                            // float4 per warp-tile
static constexpr int TILE_OUT  = 64;                             // outputs per warp-tile
static constexpr int WARPS_PER_BLK = 8;
static constexpr int THREADS   = WARPS_PER_BLK * 32;
static constexpr long long N_TILES = N_FLOATS / (TILE_F4 * 4);   // 204,800
static constexpr int N_BLOCKS = (int)(N_TILES / WARPS_PER_BLK);  // 25,600

__global__ __launch_bounds__(THREADS) void ts_return_kernel(
    const float4* __restrict__ X4, float* __restrict__ out)
{
    __shared__ float s[WARPS_PER_BLK][TILE_F4 * 4];   // 640 floats / warp

    const uint32_t w = threadIdx.x >> 5;
    const uint32_t l = threadIdx.x & 31;
    const uint32_t tile = blockIdx.x * WARPS_PER_BLK + w;

    const float4* __restrict__ p = X4 + (size_t)tile * TILE_F4;

    // 5 independent, fully coalesced 128B-per-warp loads (dense stream).
    float4 v0 = p[l];
    float4 v1 = p[32 + l];
    float4 v2 = p[64 + l];
    float4 v3 = p[96 + l];
    float4 v4 = p[128 + l];

    float4* __restrict__ sv = (float4*)s[w];
    sv[l]        = v0;
    sv[32 + l]   = v1;
    sv[64 + l]   = v2;
    sv[96 + l]   = v3;
    sv[128 + l]  = v4;
    __syncwarp();

    // Gather: output o (0..63) needs s[10o] and s[10o+9].
    const float* __restrict__ sw = s[w];
    uint32_t i0 = 10u * l;          // o = l
    uint32_t i1 = i0 + 320u;        // o = l + 32
    float r0 = __fdividef(sw[i0 + 9],  sw[i0])  - 2.0f;
    float r1 = __fdividef(sw[i1 + 9],  sw[i1])  - 2.0f;

    float* __restrict__ d = out + (size_t)tile * TILE_OUT;
    d[l]      = r0;    // coalesced 128B
    d[32 + l] = r1;    // coalesced 128B
}

extern "C" void kernel_launch(void* const* d_in, const int* in_sizes, int n_in,
                              void* d_out, int out_size)
{
    const float4* X4 = (const float4*)d_in[0];
    float* out = (float*)d_out;
    ts_return_kernel<<<N_BLOCKS, THREADS>>>(X4, out);
}